// round 15
// baseline (speedup 1.0000x reference)
#include <cuda_runtime.h>
#include <cuda_fp16.h>
#include <math.h>

#define SEQ    2048
#define DMODEL 2048
#define NHEADS 16
#define DKH    128
typedef __half fp16;

// ------------------------- scratch (device globals) -------------------------
__device__ fp16 g_in16[3 * SEQ * DMODEL];                 // [i][s][d]  (qry, key, val fp16)
__device__ fp16 g_wT[3 * NHEADS * DKH * DMODEL];          // [i][h][n][d]
__device__ fp16 g_woT[DMODEL * DMODEL];                   // [n][k]
__device__ float g_bias[3 * DMODEL];                      // [i][h*128+n]
__device__ fp16 g_qkv[3 * SEQ * DMODEL];                  // [i][s][h*128+n]
__device__ fp16 g_vT[NHEADS * DKH * SEQ];                 // [h][n][t]  (pre-scaled by 1/Z)
__device__ fp16 g_E[(size_t)NHEADS * SEQ * SEQ];          // fp16 E=exp(scores) [h][s][t]
__device__ float g_Z[NHEADS * SEQ];                       // column sums [h][t]
__device__ fp16 g_cc[SEQ * DMODEL];                       // [s][h*128+n]
__device__ float g_part[2 * SEQ * DMODEL];                // split-K partials for out-proj

// ------------------------- helpers -------------------------
__device__ __forceinline__ unsigned smem_u32(const void* p) {
    unsigned a;
    asm("{ .reg .u64 t; cvta.to.shared.u64 t, %1; cvt.u32.u64 %0, t; }" : "=r"(a) : "l"(p));
    return a;
}
// SW128 for 128-byte rows (8 x 16B granules): granule idx ^= row & 7
__device__ __forceinline__ unsigned swz(unsigned o) {
    return o ^ (((o >> 7) & 7u) << 4);
}
__device__ __forceinline__ void ldsm4(unsigned* r, unsigned addr) {
    asm volatile("ldmatrix.sync.aligned.m8n8.x4.shared.b16 {%0,%1,%2,%3}, [%4];"
        : "=r"(r[0]), "=r"(r[1]), "=r"(r[2]), "=r"(r[3]) : "r"(addr));
}
__device__ __forceinline__ void mma16816(float* d, const unsigned* a, unsigned b0, unsigned b1) {
    asm volatile("mma.sync.aligned.m16n8k16.row.col.f32.f16.f16.f32 "
        "{%0,%1,%2,%3}, {%4,%5,%6,%7}, {%8,%9}, {%0,%1,%2,%3};"
        : "+f"(d[0]), "+f"(d[1]), "+f"(d[2]), "+f"(d[3])
        : "r"(a[0]), "r"(a[1]), "r"(a[2]), "r"(a[3]), "r"(b0), "r"(b1));
}
__device__ __forceinline__ void cp16(unsigned dst, const void* src) {
    asm volatile("cp.async.cg.shared.global [%0], [%1], 16;" :: "r"(dst), "l"(src));
}
#define CP_COMMIT() asm volatile("cp.async.commit_group;" ::: "memory")
#define CP_WAIT(n)  asm volatile("cp.async.wait_group %0;" :: "n"(n) : "memory")

__device__ __forceinline__ unsigned pack_h2(float lo, float hi) {
    half2 h = __float22half2_rn(make_float2(lo, hi));
    return *(unsigned*)&h;
}

// ------------------------- fp16 warp-MMA GEMM -------------------------
// C[z][m,n] = scale * sum_k A[z][m,k]*B[z][n,k] (+ bias[z][n])
// Block tile 64(M) x 128(N), K-chunk 64, 128 threads (4 warps, 2x2 of 32x64).
// 3-stage cp.async pipeline (prefetch depth 2), 72KB smem, occ 3.
// MODE 0: fp32 C.  MODE 1: fp16 Ch.  MODE 2: merged projections (z = i*16+h), fp16 Ch.
// MODE 3: fp16 Ch = exp(scale*acc); column sums atomically added into C (= Z[h][t]).
#define BM 64
#define BN 128
#define BKC 64
#define ST_A 0
#define ST_B 8192
#define ST_STRIDE 24576
#define GSMEM 73728

template<int MODE>
__global__ void __launch_bounds__(128, 3)
mma_gemm(const fp16* __restrict__ A, const fp16* __restrict__ B,
         const float* __restrict__ bias, float* __restrict__ C, fp16* __restrict__ Ch,
         int K, int lda, long abatch, int ldb, long bbatch,
         int ldc, long cbatch, long biasbatch, float scale, int has_bias)
{
    extern __shared__ __align__(1024) char sm[];
    const unsigned sb = smem_u32(sm);
    const int tid  = threadIdx.x;
    const int lane = tid & 31;
    const int wid  = tid >> 5;
    const int wm   = wid & 1;         // 2 x 32 rows
    const int wn   = wid >> 1;        // 2 x 64 cols
    const int z    = blockIdx.z;

    long coff;
    long boff_bias;
    if (MODE == 2) {
        const int ip = z >> 4;        // input selector (q/k/v)
        const int h  = z & 15;        // head
        A += (long)ip * abatch + (long)blockIdx.y * BM * lda;
        B += (long)z * bbatch;
        coff = (long)ip * cbatch + (long)h * 128 + (long)blockIdx.y * BM * ldc;
        boff_bias = (long)z * 128;
    } else {
        A += (long)z * abatch + (long)blockIdx.y * BM * lda;
        B += (long)z * bbatch + (long)blockIdx.x * BN * ldb;
        coff = (long)z * cbatch + (long)blockIdx.y * BM * ldc + (long)blockIdx.x * BN;
        boff_bias = (long)z * biasbatch + (long)blockIdx.x * BN;
    }

    float acc[2][8][4];
#pragma unroll
    for (int mt = 0; mt < 2; mt++)
#pragma unroll
        for (int nt = 0; nt < 8; nt++)
#pragma unroll
            for (int i = 0; i < 4; i++) acc[mt][nt][i] = 0.0f;

    // cp.async coords: granule = 16B = 8 fp16. rows r0 + 16i, granule g.
    const int r0 = tid >> 3;          // 0..15
    const int g  = tid & 7;           // 0..7
    const unsigned dbase = swz((unsigned)(r0 * 128 + g * 16));
    const long sa = (long)r0 * lda + g * 8;
    const long sbk = (long)r0 * ldb + g * 8;

    // ldmatrix coords (row-constant swizzle folded in)
    const int hi = lane >> 4;         // 0/1 -> +8 cols
    const int arow[2] = { wm * 32 + (lane & 15), wm * 32 + 16 + (lane & 15) };
    const int brow[4] = { wn * 64 + (lane & 15),      wn * 64 + 16 + (lane & 15),
                          wn * 64 + 32 + (lane & 15), wn * 64 + 48 + (lane & 15) };

    const int nch = K >> 6;

#define LOAD_CHUNK(st, k0) do {                                                     \
    const unsigned b_ = sb + (st) * ST_STRIDE;                                      \
    _Pragma("unroll")                                                               \
    for (int i = 0; i < 4; i++)                                                     \
        cp16(b_ + ST_A + dbase + i * 2048, A + sa + (long)i * 16 * lda + (k0));     \
    _Pragma("unroll")                                                               \
    for (int i = 0; i < 8; i++)                                                     \
        cp16(b_ + ST_B + dbase + i * 2048, B + sbk + (long)i * 16 * ldb + (k0));    \
} while (0)

    // prologue: fill 2 stages ahead
    LOAD_CHUNK(0, 0);
    CP_COMMIT();
    if (nch > 1) {
        LOAD_CHUNK(1, BKC);
        CP_COMMIT();
    }

    int st = 0, st2 = 2;   // compute stage, next load stage
    for (int ch = 0; ch < nch; ch++) {
        if (ch + 2 < nch) {
            LOAD_CHUNK(st2, (ch + 2) * BKC);
            CP_COMMIT();
            CP_WAIT(2);
        } else if (ch + 1 < nch) {
            CP_WAIT(1);
        } else {
            CP_WAIT(0);
        }
        __syncthreads();

        const unsigned stb = sb + st * ST_STRIDE;
#pragma unroll
        for (int kk = 0; kk < 4; kk++) {
            const int cg = kk * 2 + hi;   // granule column 0..7
            unsigned a[2][4];
#pragma unroll
            for (int mt = 0; mt < 2; mt++) {
                const unsigned off = (unsigned)(arow[mt] * 128 + ((cg ^ (arow[mt] & 7)) * 16));
                ldsm4(a[mt], stb + ST_A + off);
            }
#pragma unroll
            for (int g4 = 0; g4 < 4; g4++) {
                const unsigned off = (unsigned)(brow[g4] * 128 + ((cg ^ (brow[g4] & 7)) * 16));
                unsigned bh[4];
                ldsm4(bh, stb + ST_B + off);
#pragma unroll
                for (int mt = 0; mt < 2; mt++) {
                    mma16816(acc[mt][2*g4],   a[mt], bh[0], bh[2]);
                    mma16816(acc[mt][2*g4+1], a[mt], bh[1], bh[3]);
                }
            }
        }
        __syncthreads();
        st  = (st  == 2) ? 0 : st + 1;
        st2 = (st2 == 2) ? 0 : st2 + 1;
    }
#undef LOAD_CHUNK

    // ---------------- epilogue ----------------
    const float* bz = bias + boff_bias;
    float csum[8][2];
    if (MODE == 3) {
#pragma unroll
        for (int nt = 0; nt < 8; nt++) { csum[nt][0] = 0.f; csum[nt][1] = 0.f; }
    }
#pragma unroll
    for (int mt = 0; mt < 2; mt++) {
        const int row = wm * 32 + mt * 16 + (lane >> 2);
#pragma unroll
        for (int nt = 0; nt < 8; nt++) {
            const int col = wn * 64 + nt * 8 + (lane & 3) * 2;
            float b0 = 0.f, b1 = 0.f;
            if (has_bias) { b0 = bz[col]; b1 = bz[col + 1]; }
            float x0 = fmaf(acc[mt][nt][0], scale, b0);
            float x1 = fmaf(acc[mt][nt][1], scale, b1);
            float x2 = fmaf(acc[mt][nt][2], scale, b0);
            float x3 = fmaf(acc[mt][nt][3], scale, b1);
            if (MODE == 3) {
                x0 = __expf(x0); x1 = __expf(x1); x2 = __expf(x2); x3 = __expf(x3);
                csum[nt][0] += x0 + x2;
                csum[nt][1] += x1 + x3;
            }
            if (MODE == 0) {
                float2 v01; v01.x = x0; v01.y = x1;
                float2 v23; v23.x = x2; v23.y = x3;
                *(float2*)(C + coff + (long)row * ldc + col)       = v01;
                *(float2*)(C + coff + (long)(row + 8) * ldc + col) = v23;
            } else {
                *(unsigned*)(Ch + coff + (long)row * ldc + col)       = pack_h2(x0, x1);
                *(unsigned*)(Ch + coff + (long)(row + 8) * ldc + col) = pack_h2(x2, x3);
            }
        }
    }
    if (MODE == 3) {
        // reduce column partials over the 8-lane row group, then atomic into Z (= C)
        float* Zp = C + (long)z * SEQ + (long)blockIdx.x * BN;
#pragma unroll
        for (int nt = 0; nt < 8; nt++) {
#pragma unroll
            for (int j = 0; j < 2; j++) {
                float v = csum[nt][j];
                v += __shfl_xor_sync(0xffffffffu, v, 4);
                v += __shfl_xor_sync(0xffffffffu, v, 8);
                v += __shfl_xor_sync(0xffffffffu, v, 16);
                if ((lane >> 2) == 0)
                    atomicAdd(Zp + wn * 64 + nt * 8 + (lane & 3) * 2 + j, v);
            }
        }
    }
}

// ------------------------- fp32 -> fp16: 3 tensors in one launch -------------------------
__global__ void __launch_bounds__(256)
cvt3_kernel(const float4* __restrict__ q, const float4* __restrict__ k,
            const float4* __restrict__ v, uint4* __restrict__ o, int n8)
{
    const int i = blockIdx.x * 256 + threadIdx.x;
    if (i >= n8) return;
    const int sel = blockIdx.y;
    const float4* in = (sel == 0) ? q : (sel == 1) ? k : v;
    float4 x0 = in[2*i], x1 = in[2*i + 1];
    uint4 r;
    r.x = pack_h2(x0.x, x0.y);
    r.y = pack_h2(x0.z, x0.w);
    r.z = pack_h2(x1.x, x1.y);
    r.w = pack_h2(x1.z, x1.w);
    o[(long)sel * n8 + i] = r;
}

// ------------------------- transpose+cvt 3 weight tensors in one launch -------------------------
// z = i*16+h. in: Wx[h] is [DMODEL][DKH]; out: wT[i][h] = [DKH][DMODEL].
__global__ void __launch_bounds__(256)
transpose_cvt3_kernel(const float* __restrict__ Wq, const float* __restrict__ Wk,
                      const float* __restrict__ Wv, fp16* __restrict__ o)
{
    __shared__ float tile[32][33];
    const int z = blockIdx.z;
    const int ip = z >> 4;
    const int h  = z & 15;
    const float* in = ((ip == 0) ? Wq : (ip == 1) ? Wk : Wv) + (long)h * DMODEL * DKH;
    fp16* op = o + (long)z * DKH * DMODEL;
    const int c0 = blockIdx.x * 32;
    const int r0 = blockIdx.y * 32;
    const int tx = threadIdx.x & 31;
    const int ty = threadIdx.x >> 5;
#pragma unroll
    for (int j = 0; j < 4; j++)
        tile[ty + 8 * j][tx] = in[(long)(r0 + ty + 8 * j) * DKH + c0 + tx];
    __syncthreads();
#pragma unroll
    for (int j = 0; j < 4; j++)
        op[(long)(c0 + ty + 8 * j) * DMODEL + r0 + tx] = __float2half(tile[tx][ty + 8 * j]);
}

// ------------------------- transpose + cvt (single, for Wo) -------------------------
__global__ void __launch_bounds__(256)
transpose_cvt_kernel(const float* __restrict__ in, fp16* __restrict__ o,
                     long ibatch, int istride, long obatch, int ostride)
{
    __shared__ float tile[32][33];
    const int z = blockIdx.z;
    in += (long)z * ibatch;
    o  += (long)z * obatch;
    const int c0 = blockIdx.x * 32;
    const int r0 = blockIdx.y * 32;
    const int tx = threadIdx.x & 31;
    const int ty = threadIdx.x >> 5;
#pragma unroll
    for (int j = 0; j < 4; j++)
        tile[ty + 8 * j][tx] = in[(long)(r0 + ty + 8 * j) * istride + c0 + tx];
    __syncthreads();
#pragma unroll
    for (int j = 0; j < 4; j++)
        o[(long)(c0 + ty + 8 * j) * ostride + r0 + tx] = __float2half(tile[tx][ty + 8 * j]);
}

// ------------------------- vT transpose with 1/Z fold: vT[h][n][t] = v[t][h*128+n] / Z[h][t] ----
__global__ void __launch_bounds__(256)
transpose_scale_kernel(const fp16* __restrict__ in, fp16* __restrict__ o,
                       const float* __restrict__ Z,
                       long ibatch, int istride, long obatch, int ostride)
{
    __shared__ fp16 tile[32][34];
    const int z = blockIdx.z;
    in += (long)z * ibatch;
    o  += (long)z * obatch;
    const int c0 = blockIdx.x * 32;
    const int r0 = blockIdx.y * 32;
    const int tx = threadIdx.x & 31;
    const int ty = threadIdx.x >> 5;
#pragma unroll
    for (int j = 0; j < 4; j++)
        tile[ty + 8 * j][tx] = in[(long)(r0 + ty + 8 * j) * istride + c0 + tx];
    __syncthreads();
    const float rz = 1.0f / Z[(long)z * SEQ + r0 + tx];   // t = r0+tx, constant per thread
#pragma unroll
    for (int j = 0; j < 4; j++)
        o[(long)(c0 + ty + 8 * j) * ostride + r0 + tx] =
            __float2half(__half2float(tile[tx][ty + 8 * j]) * rz);
}

// ------------------------- split-K reduce: out = p0 + p1 + bias -------------------------
__global__ void __launch_bounds__(256)
reduce_bias_kernel(const float4* __restrict__ p0, const float4* __restrict__ p1,
                   const float* __restrict__ bias, float4* __restrict__ out, int n4)
{
    const int i = blockIdx.x * 256 + threadIdx.x;
    if (i >= n4) return;
    const int col4 = i & (DMODEL / 4 - 1);
    const float4 b = ((const float4*)bias)[col4];
    float4 a = p0[i], c = p1[i];
    float4 r;
    r.x = a.x + c.x + b.x;
    r.y = a.y + c.y + b.y;
    r.z = a.z + c.z + b.z;
    r.w = a.w + c.w + b.w;
    out[i] = r;
}

// ------------------------- launch -------------------------
extern "C" void kernel_launch(void* const* d_in, const int* in_sizes, int n_in,
                              void* d_out, int out_size)
{
    const float* query = (const float*)d_in[0];
    const float* key_  = (const float*)d_in[1];
    const float* value = (const float*)d_in[2];
    const float* Wq    = (const float*)d_in[3];
    const float* bq    = (const float*)d_in[4];
    const float* Wk    = (const float*)d_in[5];
    const float* bk    = (const float*)d_in[6];
    const float* Wv    = (const float*)d_in[7];
    const float* bv    = (const float*)d_in[8];
    const float* Wo    = (const float*)d_in[9];
    const float* bo    = (const float*)d_in[10];
    float* out = (float*)d_out;

    fp16 *in16, *wT, *woT, *qkv, *vT, *E, *cc;
    float *bias, *Z, *part;
    cudaGetSymbolAddress((void**)&in16, g_in16);
    cudaGetSymbolAddress((void**)&wT,   g_wT);
    cudaGetSymbolAddress((void**)&woT,  g_woT);
    cudaGetSymbolAddress((void**)&bias, g_bias);
    cudaGetSymbolAddress((void**)&qkv,  g_qkv);
    cudaGetSymbolAddress((void**)&vT,   g_vT);
    cudaGetSymbolAddress((void**)&E,    g_E);
    cudaGetSymbolAddress((void**)&Z,    g_Z);
    cudaGetSymbolAddress((void**)&cc,   g_cc);
    cudaGetSymbolAddress((void**)&part, g_part);

    cudaFuncSetAttribute(mma_gemm<0>, cudaFuncAttributeMaxDynamicSharedMemorySize, GSMEM);
    cudaFuncSetAttribute(mma_gemm<1>, cudaFuncAttributeMaxDynamicSharedMemorySize, GSMEM);
    cudaFuncSetAttribute(mma_gemm<2>, cudaFuncAttributeMaxDynamicSharedMemorySize, GSMEM);
    cudaFuncSetAttribute(mma_gemm<3>, cudaFuncAttributeMaxDynamicSharedMemorySize, GSMEM);

    const float inv_sqrt_dk = 0.088388347648318447f;  // 1/sqrt(128)
    const long PLANE = (long)SEQ * DMODEL;

    // 0) inputs -> fp16 planes (one launch), Z zeroed
    {
        const int n8 = SEQ * DMODEL / 8;
        dim3 g(n8 / 256, 3);
        cvt3_kernel<<<g, 256>>>((const float4*)query, (const float4*)key_,
                                (const float4*)value, (uint4*)in16, n8);
    }
    cudaMemsetAsync(Z, 0, NHEADS * SEQ * sizeof(float));
    // 0b) transpose+cvt all projection weights (one launch), Wo separately
    {
        dim3 g(DKH / 32, DMODEL / 32, 48);
        transpose_cvt3_kernel<<<g, 256>>>(Wq, Wk, Wv, wT);
        dim3 go(DMODEL / 32, DMODEL / 32, 1);
        transpose_cvt_kernel<<<go, 256>>>(Wo, woT, 0L, DMODEL, 0L, DMODEL);
    }
    // 0c) pack biases into one buffer
    cudaMemcpyAsync(bias + 0 * DMODEL, bq, DMODEL * sizeof(float), cudaMemcpyDeviceToDevice);
    cudaMemcpyAsync(bias + 1 * DMODEL, bk, DMODEL * sizeof(float), cudaMemcpyDeviceToDevice);
    cudaMemcpyAsync(bias + 2 * DMODEL, bv, DMODEL * sizeof(float), cudaMemcpyDeviceToDevice);

    // 1) merged projections: z = i*16 + h, grid (1, 32, 48)
    {
        dim3 g(1, SEQ / BM, 48);
        mma_gemm<2><<<g, 128, GSMEM>>>(in16, wT, bias, nullptr, qkv,
                                       DMODEL, DMODEL, PLANE, DMODEL, (long)DKH * DMODEL,
                                       DMODEL, PLANE, 0L, 1.0f, 1);
    }

    // 2) E[h][s][t] = exp(q_h[s,:].k_h[t,:] / sqrt(dk)) -> fp16; Z[h][t] += column sums
    {
        dim3 g(SEQ / BN, SEQ / BM, NHEADS);
        mma_gemm<3><<<g, 128, GSMEM>>>(qkv + 0 * PLANE, qkv + 1 * PLANE, bias /*unused*/, Z, E,
                                       DKH, DMODEL, 128L, DMODEL, 128L,
                                       SEQ, (long)SEQ * SEQ, 0L, inv_sqrt_dk, 0);
    }

    // 3) vT[h][n][t] = v[t][h*128+n] / Z[h][t]
    {
        dim3 g(DKH / 32, SEQ / 32, NHEADS);
        transpose_scale_kernel<<<g, 256>>>(qkv + 2 * PLANE, vT, Z,
                                           (long)DKH, DMODEL, (long)DKH * SEQ, SEQ);
    }

    // 4) concat[s][h*128+n] = sum_t E[h][s][t] * vT[h][n][t]  -> fp16
    {
        dim3 g(1, SEQ / BM, NHEADS);
        mma_gemm<1><<<g, 128, GSMEM>>>(E, vT, bias /*unused*/, nullptr, cc,
                                       SEQ, SEQ, (long)SEQ * SEQ, SEQ, (long)DKH * SEQ,
                                       DMODEL, 128L, 0L, 1.0f, 0);
    }

    // 5) out-proj split-K=2: part[z] = cc[:, z*1024:(z+1)*1024] @ woT[:, z*1024:(z+1)*1024]^T
    {
        dim3 g(DMODEL / BN, SEQ / BM, 2);
        mma_gemm<0><<<g, 128, GSMEM>>>(cc, woT, bias /*unused*/, part, nullptr,
                                       1024, DMODEL, 1024L, DMODEL, 1024L,
                                       DMODEL, PLANE, 0L, 1.0f, 0);
    }
    // 5b) out = part0 + part1 + bo
    {
        const int n4 = SEQ * DMODEL / 4;
        reduce_bias_kernel<<<n4 / 256, 256>>>((const float4*)part, (const float4*)(part + PLANE),
                                              bo, (float4*)out, n4);
    }
}

// round 16
// speedup vs baseline: 1.0558x; 1.0558x over previous
#include <cuda_runtime.h>
#include <cuda_fp16.h>
#include <math.h>

#define SEQ    2048
#define DMODEL 2048
#define NHEADS 16
#define DKH    128
typedef __half fp16;

// ------------------------- scratch (device globals) -------------------------
__device__ fp16 g_in16[3 * SEQ * DMODEL];                 // [i][s][d]  (qry, key, val fp16)
__device__ fp16 g_wT[3 * NHEADS * DKH * DMODEL];          // [i][h][n][d]
__device__ fp16 g_woT[DMODEL * DMODEL];                   // [n][k]
__device__ float g_bias[3 * DMODEL];                      // [i][h*128+n]
__device__ fp16 g_qkv[3 * SEQ * DMODEL];                  // [i][s][h*128+n]
__device__ fp16 g_vT[NHEADS * DKH * SEQ];                 // [h][n][t]  (pre-scaled by 1/Z)
__device__ fp16 g_E[(size_t)NHEADS * SEQ * SEQ];          // fp16 E=exp(scores) [h][s][t]
__device__ float g_Z[NHEADS * SEQ];                       // column sums [h][t]
__device__ fp16 g_cc[SEQ * DMODEL];                       // [s][h*128+n]
__device__ float g_part[2 * SEQ * DMODEL];                // split-K partials for out-proj

// ------------------------- helpers -------------------------
__device__ __forceinline__ unsigned smem_u32(const void* p) {
    unsigned a;
    asm("{ .reg .u64 t; cvta.to.shared.u64 t, %1; cvt.u32.u64 %0, t; }" : "=r"(a) : "l"(p));
    return a;
}
// SW128 for 128-byte rows (8 x 16B granules): granule idx ^= row & 7
__device__ __forceinline__ unsigned swz(unsigned o) {
    return o ^ (((o >> 7) & 7u) << 4);
}
__device__ __forceinline__ void ldsm4(unsigned* r, unsigned addr) {
    asm volatile("ldmatrix.sync.aligned.m8n8.x4.shared.b16 {%0,%1,%2,%3}, [%4];"
        : "=r"(r[0]), "=r"(r[1]), "=r"(r[2]), "=r"(r[3]) : "r"(addr));
}
__device__ __forceinline__ void mma16816(float* d, const unsigned* a, unsigned b0, unsigned b1) {
    asm volatile("mma.sync.aligned.m16n8k16.row.col.f32.f16.f16.f32 "
        "{%0,%1,%2,%3}, {%4,%5,%6,%7}, {%8,%9}, {%0,%1,%2,%3};"
        : "+f"(d[0]), "+f"(d[1]), "+f"(d[2]), "+f"(d[3])
        : "r"(a[0]), "r"(a[1]), "r"(a[2]), "r"(a[3]), "r"(b0), "r"(b1));
}
__device__ __forceinline__ void cp16(unsigned dst, const void* src) {
    asm volatile("cp.async.cg.shared.global [%0], [%1], 16;" :: "r"(dst), "l"(src));
}
#define CP_COMMIT() asm volatile("cp.async.commit_group;" ::: "memory")
#define CP_WAIT(n)  asm volatile("cp.async.wait_group %0;" :: "n"(n) : "memory")

__device__ __forceinline__ unsigned pack_h2(float lo, float hi) {
    half2 h = __float22half2_rn(make_float2(lo, hi));
    return *(unsigned*)&h;
}

// ------------------------- fp16 warp-MMA GEMM -------------------------
// C[z][m,n] = scale * sum_k A[z][m,k]*B[z][n,k] (+ bias[z][n])
// Block tile 64(M) x 128(N), K-chunk 64, 128 threads (4 warps, 2x2 of 32x64), occ 4.
// MODE 0: fp32 C.  MODE 1: fp16 Ch.  MODE 2: merged projections (z = i*16+h), fp16 Ch.
// MODE 3: fp16 Ch = exp(scale*acc); column sums atomically added into C (= Z[h][t]).
#define BM 64
#define BN 128
#define BKC 64
#define ST_A 0
#define ST_B 8192
#define ST_STRIDE 24576
#define GSMEM 49152

template<int MODE>
__global__ void __launch_bounds__(128, 4)
mma_gemm(const fp16* __restrict__ A, const fp16* __restrict__ B,
         const float* __restrict__ bias, float* __restrict__ C, fp16* __restrict__ Ch,
         int K, int lda, long abatch, int ldb, long bbatch,
         int ldc, long cbatch, long biasbatch, float scale, int has_bias)
{
    extern __shared__ __align__(1024) char sm[];
    const unsigned sb = smem_u32(sm);
    const int tid  = threadIdx.x;
    const int lane = tid & 31;
    const int wid  = tid >> 5;
    const int wm   = wid & 1;         // 2 x 32 rows
    const int wn   = wid >> 1;        // 2 x 64 cols
    const int z    = blockIdx.z;

    long coff;
    long boff_bias;
    if (MODE == 2) {
        const int ip = z >> 4;        // input selector (q/k/v)
        const int h  = z & 15;        // head
        A += (long)ip * abatch + (long)blockIdx.y * BM * lda;
        B += (long)z * bbatch;
        coff = (long)ip * cbatch + (long)h * 128 + (long)blockIdx.y * BM * ldc;
        boff_bias = (long)z * 128;
    } else {
        A += (long)z * abatch + (long)blockIdx.y * BM * lda;
        B += (long)z * bbatch + (long)blockIdx.x * BN * ldb;
        coff = (long)z * cbatch + (long)blockIdx.y * BM * ldc + (long)blockIdx.x * BN;
        boff_bias = (long)z * biasbatch + (long)blockIdx.x * BN;
    }

    float acc[2][8][4];
#pragma unroll
    for (int mt = 0; mt < 2; mt++)
#pragma unroll
        for (int nt = 0; nt < 8; nt++)
#pragma unroll
            for (int i = 0; i < 4; i++) acc[mt][nt][i] = 0.0f;

    // cp.async coords: granule = 16B = 8 fp16. rows r0 + 16i, granule g.
    const int r0 = tid >> 3;          // 0..15
    const int g  = tid & 7;           // 0..7
    const unsigned dbase = swz((unsigned)(r0 * 128 + g * 16));
    const long sa = (long)r0 * lda + g * 8;
    const long sbk = (long)r0 * ldb + g * 8;

    // ldmatrix coords (row-constant swizzle folded in)
    const int hi = lane >> 4;         // 0/1 -> +8 cols
    const int arow[2] = { wm * 32 + (lane & 15), wm * 32 + 16 + (lane & 15) };
    const int brow[4] = { wn * 64 + (lane & 15),      wn * 64 + 16 + (lane & 15),
                          wn * 64 + 32 + (lane & 15), wn * 64 + 48 + (lane & 15) };

    const int nch = K >> 6;

#define LOAD_CHUNK(st, k0) do {                                                     \
    const unsigned b_ = sb + (st) * ST_STRIDE;                                      \
    _Pragma("unroll")                                                               \
    for (int i = 0; i < 4; i++)                                                     \
        cp16(b_ + ST_A + dbase + i * 2048, A + sa + (long)i * 16 * lda + (k0));     \
    _Pragma("unroll")                                                               \
    for (int i = 0; i < 8; i++)                                                     \
        cp16(b_ + ST_B + dbase + i * 2048, B + sbk + (long)i * 16 * ldb + (k0));    \
} while (0)

    LOAD_CHUNK(0, 0);
    CP_COMMIT();

    for (int ch = 0; ch < nch; ch++) {
        if (ch + 1 < nch) {
            LOAD_CHUNK((ch + 1) & 1, (ch + 1) * BKC);
            CP_COMMIT();
            CP_WAIT(1);
        } else {
            CP_WAIT(0);
        }
        __syncthreads();

        const unsigned stb = sb + (ch & 1) * ST_STRIDE;
#pragma unroll
        for (int kk = 0; kk < 4; kk++) {
            const int cg = kk * 2 + hi;   // granule column 0..7
            unsigned a[2][4];
#pragma unroll
            for (int mt = 0; mt < 2; mt++) {
                const unsigned off = (unsigned)(arow[mt] * 128 + ((cg ^ (arow[mt] & 7)) * 16));
                ldsm4(a[mt], stb + ST_A + off);
            }
#pragma unroll
            for (int g4 = 0; g4 < 4; g4++) {
                const unsigned off = (unsigned)(brow[g4] * 128 + ((cg ^ (brow[g4] & 7)) * 16));
                unsigned bh[4];
                ldsm4(bh, stb + ST_B + off);
#pragma unroll
                for (int mt = 0; mt < 2; mt++) {
                    mma16816(acc[mt][2*g4],   a[mt], bh[0], bh[2]);
                    mma16816(acc[mt][2*g4+1], a[mt], bh[1], bh[3]);
                }
            }
        }
        __syncthreads();
    }
#undef LOAD_CHUNK

    // ---------------- epilogue ----------------
    const float* bz = bias + boff_bias;
    float csum[8][2];
    if (MODE == 3) {
#pragma unroll
        for (int nt = 0; nt < 8; nt++) { csum[nt][0] = 0.f; csum[nt][1] = 0.f; }
    }
#pragma unroll
    for (int mt = 0; mt < 2; mt++) {
        const int row = wm * 32 + mt * 16 + (lane >> 2);
#pragma unroll
        for (int nt = 0; nt < 8; nt++) {
            const int col = wn * 64 + nt * 8 + (lane & 3) * 2;
            float b0 = 0.f, b1 = 0.f;
            if (has_bias) { b0 = bz[col]; b1 = bz[col + 1]; }
            float x0 = fmaf(acc[mt][nt][0], scale, b0);
            float x1 = fmaf(acc[mt][nt][1], scale, b1);
            float x2 = fmaf(acc[mt][nt][2], scale, b0);
            float x3 = fmaf(acc[mt][nt][3], scale, b1);
            if (MODE == 3) {
                x0 = __expf(x0); x1 = __expf(x1); x2 = __expf(x2); x3 = __expf(x3);
                csum[nt][0] += x0 + x2;
                csum[nt][1] += x1 + x3;
            }
            if (MODE == 0) {
                float2 v01; v01.x = x0; v01.y = x1;
                float2 v23; v23.x = x2; v23.y = x3;
                *(float2*)(C + coff + (long)row * ldc + col)       = v01;
                *(float2*)(C + coff + (long)(row + 8) * ldc + col) = v23;
            } else {
                *(unsigned*)(Ch + coff + (long)row * ldc + col)       = pack_h2(x0, x1);
                *(unsigned*)(Ch + coff + (long)(row + 8) * ldc + col) = pack_h2(x2, x3);
            }
        }
    }
    if (MODE == 3) {
        // reduce column partials over the 8-lane row group, then atomic into Z (= C)
        float* Zp = C + (long)z * SEQ + (long)blockIdx.x * BN;
#pragma unroll
        for (int nt = 0; nt < 8; nt++) {
#pragma unroll
            for (int j = 0; j < 2; j++) {
                float v = csum[nt][j];
                v += __shfl_xor_sync(0xffffffffu, v, 4);
                v += __shfl_xor_sync(0xffffffffu, v, 8);
                v += __shfl_xor_sync(0xffffffffu, v, 16);
                if ((lane >> 2) == 0)
                    atomicAdd(Zp + wn * 64 + nt * 8 + (lane & 3) * 2 + j, v);
            }
        }
    }
}

// ------------------------- fp32 -> fp16: 3 tensors in one launch -------------------------
__global__ void __launch_bounds__(256)
cvt3_kernel(const float4* __restrict__ q, const float4* __restrict__ k,
            const float4* __restrict__ v, uint4* __restrict__ o, int n8)
{
    const int i = blockIdx.x * 256 + threadIdx.x;
    if (i >= n8) return;
    const int sel = blockIdx.y;
    const float4* in = (sel == 0) ? q : (sel == 1) ? k : v;
    float4 x0 = in[2*i], x1 = in[2*i + 1];
    uint4 r;
    r.x = pack_h2(x0.x, x0.y);
    r.y = pack_h2(x0.z, x0.w);
    r.z = pack_h2(x1.x, x1.y);
    r.w = pack_h2(x1.z, x1.w);
    o[(long)sel * n8 + i] = r;
}

// ------------------------- pack biases + zero Z in one tiny launch -------------------------
__global__ void __launch_bounds__(256)
pack_bias_kernel(const float* __restrict__ bq, const float* __restrict__ bk,
                 const float* __restrict__ bv, float* __restrict__ bias,
                 float* __restrict__ Z)
{
    const int i = blockIdx.x * 256 + threadIdx.x;
    if (i < DMODEL) {
        bias[i]              = bq[i];
        bias[DMODEL + i]     = bk[i];
        bias[2 * DMODEL + i] = bv[i];
    }
    // zero Z (NHEADS*SEQ = 32768 floats; grid covers it)
    if (i < NHEADS * SEQ) Z[i] = 0.0f;
}

// ------------------------- transpose+cvt 3 weight tensors in one launch -------------------------
// z = i*16+h. in: Wx[h] is [DMODEL][DKH]; out: wT[i][h] = [DKH][DMODEL].
__global__ void __launch_bounds__(256)
transpose_cvt3_kernel(const float* __restrict__ Wq, const float* __restrict__ Wk,
                      const float* __restrict__ Wv, fp16* __restrict__ o)
{
    __shared__ float tile[32][33];
    const int z = blockIdx.z;
    const int ip = z >> 4;
    const int h  = z & 15;
    const float* in = ((ip == 0) ? Wq : (ip == 1) ? Wk : Wv) + (long)h * DMODEL * DKH;
    fp16* op = o + (long)z * DKH * DMODEL;
    const int c0 = blockIdx.x * 32;
    const int r0 = blockIdx.y * 32;
    const int tx = threadIdx.x & 31;
    const int ty = threadIdx.x >> 5;
#pragma unroll
    for (int j = 0; j < 4; j++)
        tile[ty + 8 * j][tx] = in[(long)(r0 + ty + 8 * j) * DKH + c0 + tx];
    __syncthreads();
#pragma unroll
    for (int j = 0; j < 4; j++)
        op[(long)(c0 + ty + 8 * j) * DMODEL + r0 + tx] = __float2half(tile[tx][ty + 8 * j]);
}

// ------------------------- transpose + cvt (single, for Wo) -------------------------
__global__ void __launch_bounds__(256)
transpose_cvt_kernel(const float* __restrict__ in, fp16* __restrict__ o,
                     long ibatch, int istride, long obatch, int ostride)
{
    __shared__ float tile[32][33];
    const int z = blockIdx.z;
    in += (long)z * ibatch;
    o  += (long)z * obatch;
    const int c0 = blockIdx.x * 32;
    const int r0 = blockIdx.y * 32;
    const int tx = threadIdx.x & 31;
    const int ty = threadIdx.x >> 5;
#pragma unroll
    for (int j = 0; j < 4; j++)
        tile[ty + 8 * j][tx] = in[(long)(r0 + ty + 8 * j) * istride + c0 + tx];
    __syncthreads();
#pragma unroll
    for (int j = 0; j < 4; j++)
        o[(long)(c0 + ty + 8 * j) * ostride + r0 + tx] = __float2half(tile[tx][ty + 8 * j]);
}

// ------------------------- vT transpose with 1/Z fold: vT[h][n][t] = v[t][h*128+n] / Z[h][t] ----
__global__ void __launch_bounds__(256)
transpose_scale_kernel(const fp16* __restrict__ in, fp16* __restrict__ o,
                       const float* __restrict__ Z,
                       long ibatch, int istride, long obatch, int ostride)
{
    __shared__ fp16 tile[32][34];
    const int z = blockIdx.z;
    in += (long)z * ibatch;
    o  += (long)z * obatch;
    const int c0 = blockIdx.x * 32;
    const int r0 = blockIdx.y * 32;
    const int tx = threadIdx.x & 31;
    const int ty = threadIdx.x >> 5;
#pragma unroll
    for (int j = 0; j < 4; j++)
        tile[ty + 8 * j][tx] = in[(long)(r0 + ty + 8 * j) * istride + c0 + tx];
    __syncthreads();
    const float rz = 1.0f / Z[(long)z * SEQ + r0 + tx];   // t = r0+tx, constant per thread
#pragma unroll
    for (int j = 0; j < 4; j++)
        o[(long)(c0 + ty + 8 * j) * ostride + r0 + tx] =
            __float2half(__half2float(tile[tx][ty + 8 * j]) * rz);
}

// ------------------------- split-K reduce: out = p0 + p1 + bias -------------------------
__global__ void __launch_bounds__(256)
reduce_bias_kernel(const float4* __restrict__ p0, const float4* __restrict__ p1,
                   const float* __restrict__ bias, float4* __restrict__ out, int n4)
{
    const int i = blockIdx.x * 256 + threadIdx.x;
    if (i >= n4) return;
    const int col4 = i & (DMODEL / 4 - 1);
    const float4 b = ((const float4*)bias)[col4];
    float4 a = p0[i], c = p1[i];
    float4 r;
    r.x = a.x + c.x + b.x;
    r.y = a.y + c.y + b.y;
    r.z = a.z + c.z + b.z;
    r.w = a.w + c.w + b.w;
    out[i] = r;
}

// ------------------------- launch -------------------------
extern "C" void kernel_launch(void* const* d_in, const int* in_sizes, int n_in,
                              void* d_out, int out_size)
{
    const float* query = (const float*)d_in[0];
    const float* key_  = (const float*)d_in[1];
    const float* value = (const float*)d_in[2];
    const float* Wq    = (const float*)d_in[3];
    const float* bq    = (const float*)d_in[4];
    const float* Wk    = (const float*)d_in[5];
    const float* bk    = (const float*)d_in[6];
    const float* Wv    = (const float*)d_in[7];
    const float* bv    = (const float*)d_in[8];
    const float* Wo    = (const float*)d_in[9];
    const float* bo    = (const float*)d_in[10];
    float* out = (float*)d_out;

    fp16 *in16, *wT, *woT, *qkv, *vT, *E, *cc;
    float *bias, *Z, *part;
    cudaGetSymbolAddress((void**)&in16, g_in16);
    cudaGetSymbolAddress((void**)&wT,   g_wT);
    cudaGetSymbolAddress((void**)&woT,  g_woT);
    cudaGetSymbolAddress((void**)&bias, g_bias);
    cudaGetSymbolAddress((void**)&qkv,  g_qkv);
    cudaGetSymbolAddress((void**)&vT,   g_vT);
    cudaGetSymbolAddress((void**)&E,    g_E);
    cudaGetSymbolAddress((void**)&Z,    g_Z);
    cudaGetSymbolAddress((void**)&cc,   g_cc);
    cudaGetSymbolAddress((void**)&part, g_part);

    cudaFuncSetAttribute(mma_gemm<0>, cudaFuncAttributeMaxDynamicSharedMemorySize, GSMEM);
    cudaFuncSetAttribute(mma_gemm<1>, cudaFuncAttributeMaxDynamicSharedMemorySize, GSMEM);
    cudaFuncSetAttribute(mma_gemm<2>, cudaFuncAttributeMaxDynamicSharedMemorySize, GSMEM);
    cudaFuncSetAttribute(mma_gemm<3>, cudaFuncAttributeMaxDynamicSharedMemorySize, GSMEM);

    const float inv_sqrt_dk = 0.088388347648318447f;  // 1/sqrt(128)
    const long PLANE = (long)SEQ * DMODEL;

    // 0) inputs -> fp16 planes (one launch); bias pack + Z zero (one tiny launch)
    {
        const int n8 = SEQ * DMODEL / 8;
        dim3 g(n8 / 256, 3);
        cvt3_kernel<<<g, 256>>>((const float4*)query, (const float4*)key_,
                                (const float4*)value, (uint4*)in16, n8);
    }
    pack_bias_kernel<<<(NHEADS * SEQ + 255) / 256, 256>>>(bq, bk, bv, bias, Z);
    // 0b) transpose+cvt all projection weights (one launch), Wo separately
    {
        dim3 g(DKH / 32, DMODEL / 32, 48);
        transpose_cvt3_kernel<<<g, 256>>>(Wq, Wk, Wv, wT);
        dim3 go(DMODEL / 32, DMODEL / 32, 1);
        transpose_cvt_kernel<<<go, 256>>>(Wo, woT, 0L, DMODEL, 0L, DMODEL);
    }

    // 1) merged projections: z = i*16 + h, grid (1, 32, 48)
    {
        dim3 g(1, SEQ / BM, 48);
        mma_gemm<2><<<g, 128, GSMEM>>>(in16, wT, bias, nullptr, qkv,
                                       DMODEL, DMODEL, PLANE, DMODEL, (long)DKH * DMODEL,
                                       DMODEL, PLANE, 0L, 1.0f, 1);
    }

    // 2) E[h][s][t] = exp(q_h[s,:].k_h[t,:] / sqrt(dk)) -> fp16; Z[h][t] += column sums
    {
        dim3 g(SEQ / BN, SEQ / BM, NHEADS);
        mma_gemm<3><<<g, 128, GSMEM>>>(qkv + 0 * PLANE, qkv + 1 * PLANE, bias /*unused*/, Z, E,
                                       DKH, DMODEL, 128L, DMODEL, 128L,
                                       SEQ, (long)SEQ * SEQ, 0L, inv_sqrt_dk, 0);
    }

    // 3) vT[h][n][t] = v[t][h*128+n] / Z[h][t]
    {
        dim3 g(DKH / 32, SEQ / 32, NHEADS);
        transpose_scale_kernel<<<g, 256>>>(qkv + 2 * PLANE, vT, Z,
                                           (long)DKH, DMODEL, (long)DKH * SEQ, SEQ);
    }

    // 4) concat[s][h*128+n] = sum_t E[h][s][t] * vT[h][n][t]  -> fp16
    {
        dim3 g(1, SEQ / BM, NHEADS);
        mma_gemm<1><<<g, 128, GSMEM>>>(E, vT, bias /*unused*/, nullptr, cc,
                                       SEQ, SEQ, (long)SEQ * SEQ, SEQ, (long)DKH * SEQ,
                                       DMODEL, 128L, 0L, 1.0f, 0);
    }

    // 5) out-proj split-K=2: part[z] = cc[:, z*1024:(z+1)*1024] @ woT[:, z*1024:(z+1)*1024]^T
    {
        dim3 g(DMODEL / BN, SEQ / BM, 2);
        mma_gemm<0><<<g, 128, GSMEM>>>(cc, woT, bias /*unused*/, part, nullptr,
                                       1024, DMODEL, 1024L, DMODEL, 1024L,
                                       DMODEL, PLANE, 0L, 1.0f, 0);
    }
    // 5b) out = part0 + part1 + bo
    {
        const int n4 = SEQ * DMODEL / 4;
        reduce_bias_kernel<<<n4 / 256, 256>>>((const float4*)part, (const float4*)(part + PLANE),
                                              bo, (float4*)out, n4);
    }
}

// round 17
// speedup vs baseline: 1.0679x; 1.0115x over previous
#include <cuda_runtime.h>
#include <cuda_fp16.h>
#include <math.h>

#define SEQ    2048
#define DMODEL 2048
#define NHEADS 16
#define DKH    128
typedef __half fp16;

// ------------------------- scratch (device globals) -------------------------
__device__ fp16 g_in16[3 * SEQ * DMODEL];                 // [i][s][d]  (qry, key, val fp16)
__device__ fp16 g_wT[3 * NHEADS * DKH * DMODEL];          // [i][h][n][d]
__device__ fp16 g_woT[DMODEL * DMODEL];                   // [n][k]
__device__ float g_bias[3 * DMODEL];                      // [i][h*128+n]
__device__ fp16 g_qkv[3 * SEQ * DMODEL];                  // [i][s][h*128+n]
__device__ fp16 g_vT[NHEADS * DKH * SEQ];                 // [h][n][t]  (pre-scaled by 1/Z)
__device__ fp16 g_E[(size_t)NHEADS * SEQ * SEQ];          // fp16 E=exp(scores) [h][s][t]
__device__ float g_Z[NHEADS * SEQ];                       // column sums [h][t]
__device__ fp16 g_cc[SEQ * DMODEL];                       // [s][h*128+n]
__device__ float g_part[2 * SEQ * DMODEL];                // split-K partials for out-proj

// ------------------------- helpers -------------------------
__device__ __forceinline__ unsigned smem_u32(const void* p) {
    unsigned a;
    asm("{ .reg .u64 t; cvta.to.shared.u64 t, %1; cvt.u32.u64 %0, t; }" : "=r"(a) : "l"(p));
    return a;
}
// SW128 for 128-byte rows (8 x 16B granules): granule idx ^= row & 7
__device__ __forceinline__ unsigned swz(unsigned o) {
    return o ^ (((o >> 7) & 7u) << 4);
}
__device__ __forceinline__ void ldsm4(unsigned* r, unsigned addr) {
    asm volatile("ldmatrix.sync.aligned.m8n8.x4.shared.b16 {%0,%1,%2,%3}, [%4];"
        : "=r"(r[0]), "=r"(r[1]), "=r"(r[2]), "=r"(r[3]) : "r"(addr));
}
__device__ __forceinline__ void mma16816(float* d, const unsigned* a, unsigned b0, unsigned b1) {
    asm volatile("mma.sync.aligned.m16n8k16.row.col.f32.f16.f16.f32 "
        "{%0,%1,%2,%3}, {%4,%5,%6,%7}, {%8,%9}, {%0,%1,%2,%3};"
        : "+f"(d[0]), "+f"(d[1]), "+f"(d[2]), "+f"(d[3])
        : "r"(a[0]), "r"(a[1]), "r"(a[2]), "r"(a[3]), "r"(b0), "r"(b1));
}
__device__ __forceinline__ void cp16(unsigned dst, const void* src) {
    asm volatile("cp.async.cg.shared.global [%0], [%1], 16;" :: "r"(dst), "l"(src));
}
#define CP_COMMIT() asm volatile("cp.async.commit_group;" ::: "memory")
#define CP_WAIT(n)  asm volatile("cp.async.wait_group %0;" :: "n"(n) : "memory")

__device__ __forceinline__ unsigned pack_h2(float lo, float hi) {
    half2 h = __float22half2_rn(make_float2(lo, hi));
    return *(unsigned*)&h;
}

// ------------------------- fp16 warp-MMA GEMM -------------------------
// C[z][m,n] = scale * sum_k A[z][m,k]*B[z][n,k] (+ bias[z][n])
// Block tile 64(M) x 128(N), K-chunk 64, 128 threads (4 warps, 2x2 of 32x64), occ 4.
// MODE 0: fp32 C.  MODE 1: fp16 Ch.  MODE 2: merged projections (z = i*16+h), fp16 Ch.
// MODE 3: fp16 Ch = exp(scale*acc); column sums atomically added into C (= Z[h][t]).
#define BM 64
#define BN 128
#define BKC 64
#define ST_A 0
#define ST_B 8192
#define ST_STRIDE 24576
#define GSMEM 49152

template<int MODE>
__global__ void __launch_bounds__(128, 4)
mma_gemm(const fp16* __restrict__ A, const fp16* __restrict__ B,
         const float* __restrict__ bias, float* __restrict__ C, fp16* __restrict__ Ch,
         int K, int lda, long abatch, int ldb, long bbatch,
         int ldc, long cbatch, long biasbatch, float scale, int has_bias)
{
    extern __shared__ __align__(1024) char sm[];
    const unsigned sb = smem_u32(sm);
    const int tid  = threadIdx.x;
    const int lane = tid & 31;
    const int wid  = tid >> 5;
    const int wm   = wid & 1;         // 2 x 32 rows
    const int wn   = wid >> 1;        // 2 x 64 cols
    const int z    = blockIdx.z;

    long coff;
    long boff_bias;
    if (MODE == 2) {
        const int ip = z >> 4;        // input selector (q/k/v)
        const int h  = z & 15;        // head
        A += (long)ip * abatch + (long)blockIdx.y * BM * lda;
        B += (long)z * bbatch;
        coff = (long)ip * cbatch + (long)h * 128 + (long)blockIdx.y * BM * ldc;
        boff_bias = (long)z * 128;
    } else {
        A += (long)z * abatch + (long)blockIdx.y * BM * lda;
        B += (long)z * bbatch + (long)blockIdx.x * BN * ldb;
        coff = (long)z * cbatch + (long)blockIdx.y * BM * ldc + (long)blockIdx.x * BN;
        boff_bias = (long)z * biasbatch + (long)blockIdx.x * BN;
    }

    float acc[2][8][4];
#pragma unroll
    for (int mt = 0; mt < 2; mt++)
#pragma unroll
        for (int nt = 0; nt < 8; nt++)
#pragma unroll
            for (int i = 0; i < 4; i++) acc[mt][nt][i] = 0.0f;

    // cp.async coords: granule = 16B = 8 fp16. rows r0 + 16i, granule g.
    const int r0 = tid >> 3;          // 0..15
    const int g  = tid & 7;           // 0..7
    const unsigned dbase = swz((unsigned)(r0 * 128 + g * 16));
    const long sa = (long)r0 * lda + g * 8;
    const long sbk = (long)r0 * ldb + g * 8;

    // ldmatrix coords (row-constant swizzle folded in)
    const int hi = lane >> 4;         // 0/1 -> +8 cols
    const int arow[2] = { wm * 32 + (lane & 15), wm * 32 + 16 + (lane & 15) };
    const int brow[4] = { wn * 64 + (lane & 15),      wn * 64 + 16 + (lane & 15),
                          wn * 64 + 32 + (lane & 15), wn * 64 + 48 + (lane & 15) };

    const int nch = K >> 6;

#define LOAD_CHUNK(st, k0) do {                                                     \
    const unsigned b_ = sb + (st) * ST_STRIDE;                                      \
    _Pragma("unroll")                                                               \
    for (int i = 0; i < 4; i++)                                                     \
        cp16(b_ + ST_A + dbase + i * 2048, A + sa + (long)i * 16 * lda + (k0));     \
    _Pragma("unroll")                                                               \
    for (int i = 0; i < 8; i++)                                                     \
        cp16(b_ + ST_B + dbase + i * 2048, B + sbk + (long)i * 16 * ldb + (k0));    \
} while (0)

    LOAD_CHUNK(0, 0);
    CP_COMMIT();

    for (int ch = 0; ch < nch; ch++) {
        if (ch + 1 < nch) {
            LOAD_CHUNK((ch + 1) & 1, (ch + 1) * BKC);
            CP_COMMIT();
            CP_WAIT(1);
        } else {
            CP_WAIT(0);
        }
        __syncthreads();

        const unsigned stb = sb + (ch & 1) * ST_STRIDE;
#pragma unroll
        for (int kk = 0; kk < 4; kk++) {
            const int cg = kk * 2 + hi;   // granule column 0..7
            unsigned a[2][4];
#pragma unroll
            for (int mt = 0; mt < 2; mt++) {
                const unsigned off = (unsigned)(arow[mt] * 128 + ((cg ^ (arow[mt] & 7)) * 16));
                ldsm4(a[mt], stb + ST_A + off);
            }
#pragma unroll
            for (int g4 = 0; g4 < 4; g4++) {
                const unsigned off = (unsigned)(brow[g4] * 128 + ((cg ^ (brow[g4] & 7)) * 16));
                unsigned bh[4];
                ldsm4(bh, stb + ST_B + off);
#pragma unroll
                for (int mt = 0; mt < 2; mt++) {
                    mma16816(acc[mt][2*g4],   a[mt], bh[0], bh[2]);
                    mma16816(acc[mt][2*g4+1], a[mt], bh[1], bh[3]);
                }
            }
        }
        __syncthreads();
    }
#undef LOAD_CHUNK

    // ---------------- epilogue ----------------
    const float* bz = bias + boff_bias;
    float csum[8][2];
    if (MODE == 3) {
#pragma unroll
        for (int nt = 0; nt < 8; nt++) { csum[nt][0] = 0.f; csum[nt][1] = 0.f; }
    }
#pragma unroll
    for (int mt = 0; mt < 2; mt++) {
        const int row = wm * 32 + mt * 16 + (lane >> 2);
#pragma unroll
        for (int nt = 0; nt < 8; nt++) {
            const int col = wn * 64 + nt * 8 + (lane & 3) * 2;
            float b0 = 0.f, b1 = 0.f;
            if (has_bias) { b0 = bz[col]; b1 = bz[col + 1]; }
            float x0 = fmaf(acc[mt][nt][0], scale, b0);
            float x1 = fmaf(acc[mt][nt][1], scale, b1);
            float x2 = fmaf(acc[mt][nt][2], scale, b0);
            float x3 = fmaf(acc[mt][nt][3], scale, b1);
            if (MODE == 3) {
                x0 = __expf(x0); x1 = __expf(x1); x2 = __expf(x2); x3 = __expf(x3);
                csum[nt][0] += x0 + x2;
                csum[nt][1] += x1 + x3;
            }
            if (MODE == 0) {
                float2 v01; v01.x = x0; v01.y = x1;
                float2 v23; v23.x = x2; v23.y = x3;
                *(float2*)(C + coff + (long)row * ldc + col)       = v01;
                *(float2*)(C + coff + (long)(row + 8) * ldc + col) = v23;
            } else {
                *(unsigned*)(Ch + coff + (long)row * ldc + col)       = pack_h2(x0, x1);
                *(unsigned*)(Ch + coff + (long)(row + 8) * ldc + col) = pack_h2(x2, x3);
            }
        }
    }
    if (MODE == 3) {
        // reduce column partials over the 8-lane row group, then atomic into Z (= C)
        float* Zp = C + (long)z * SEQ + (long)blockIdx.x * BN;
#pragma unroll
        for (int nt = 0; nt < 8; nt++) {
#pragma unroll
            for (int j = 0; j < 2; j++) {
                float v = csum[nt][j];
                v += __shfl_xor_sync(0xffffffffu, v, 4);
                v += __shfl_xor_sync(0xffffffffu, v, 8);
                v += __shfl_xor_sync(0xffffffffu, v, 16);
                if ((lane >> 2) == 0)
                    atomicAdd(Zp + wn * 64 + nt * 8 + (lane & 3) * 2 + j, v);
            }
        }
    }
}

// ------------------------- fp32 -> fp16 (3 tensors) + bias pack + Z zero, one launch ----------
// grid (n8/256, 4): y<3 converts tensor y; y==3 packs biases and zeros Z.
__global__ void __launch_bounds__(256)
cvt3b_kernel(const float4* __restrict__ q, const float4* __restrict__ k,
             const float4* __restrict__ v, uint4* __restrict__ o, int n8,
             const float* __restrict__ bq, const float* __restrict__ bk,
             const float* __restrict__ bv, float* __restrict__ bias,
             float* __restrict__ Z)
{
    const int sel = blockIdx.y;
    const int i = blockIdx.x * 256 + threadIdx.x;
    if (sel == 3) {
        if (i < DMODEL) {
            bias[i]              = bq[i];
            bias[DMODEL + i]     = bk[i];
            bias[2 * DMODEL + i] = bv[i];
        }
        if (i < NHEADS * SEQ) Z[i] = 0.0f;
        return;
    }
    if (i >= n8) return;
    const float4* in = (sel == 0) ? q : (sel == 1) ? k : v;
    float4 x0 = in[2*i], x1 = in[2*i + 1];
    uint4 r;
    r.x = pack_h2(x0.x, x0.y);
    r.y = pack_h2(x0.z, x0.w);
    r.z = pack_h2(x1.x, x1.y);
    r.w = pack_h2(x1.z, x1.w);
    o[(long)sel * n8 + i] = r;
}

// ------------------------- all weight transposes in ONE launch -------------------------
// Flattened grid: blocks [0, 12288) = projection weights (Wq/Wk/Wv, z=i*16+h, 4x64 tiles);
//                 blocks [12288, 16384) = Wo (64x64 tiles of 32x32).
__global__ void __launch_bounds__(256)
transpose_all_kernel(const float* __restrict__ Wq, const float* __restrict__ Wk,
                     const float* __restrict__ Wv, const float* __restrict__ Wo,
                     fp16* __restrict__ wT, fp16* __restrict__ woT)
{
    __shared__ float tile[32][33];
    const int tx = threadIdx.x & 31;
    const int ty = threadIdx.x >> 5;
    const int id = blockIdx.x;

    const float* in;
    fp16* op;
    int istride, ostride, c0, r0;
    if (id < 12288) {
        const int bx = id & 3;            // DKH/32 tiles
        const int by = (id >> 2) & 63;    // DMODEL/32 tiles
        const int z  = id >> 8;           // 0..47 = i*16+h
        const int ip = z >> 4;
        const int h  = z & 15;
        in = ((ip == 0) ? Wq : (ip == 1) ? Wk : Wv) + (long)h * DMODEL * DKH;
        op = wT + (long)z * DKH * DMODEL;
        istride = DKH; ostride = DMODEL;
        c0 = bx * 32; r0 = by * 32;
    } else {
        const int wid2 = id - 12288;
        const int bx = wid2 & 63;
        const int by = wid2 >> 6;
        in = Wo; op = woT;
        istride = DMODEL; ostride = DMODEL;
        c0 = bx * 32; r0 = by * 32;
    }

#pragma unroll
    for (int j = 0; j < 4; j++)
        tile[ty + 8 * j][tx] = in[(long)(r0 + ty + 8 * j) * istride + c0 + tx];
    __syncthreads();
#pragma unroll
    for (int j = 0; j < 4; j++)
        op[(long)(c0 + ty + 8 * j) * ostride + r0 + tx] = __float2half(tile[tx][ty + 8 * j]);
}

// ------------------------- vT transpose with 1/Z fold: vT[h][n][t] = v[t][h*128+n] / Z[h][t] ----
__global__ void __launch_bounds__(256)
transpose_scale_kernel(const fp16* __restrict__ in, fp16* __restrict__ o,
                       const float* __restrict__ Z,
                       long ibatch, int istride, long obatch, int ostride)
{
    __shared__ fp16 tile[32][34];
    const int z = blockIdx.z;
    in += (long)z * ibatch;
    o  += (long)z * obatch;
    const int c0 = blockIdx.x * 32;
    const int r0 = blockIdx.y * 32;
    const int tx = threadIdx.x & 31;
    const int ty = threadIdx.x >> 5;
#pragma unroll
    for (int j = 0; j < 4; j++)
        tile[ty + 8 * j][tx] = in[(long)(r0 + ty + 8 * j) * istride + c0 + tx];
    __syncthreads();
    const float rz = 1.0f / Z[(long)z * SEQ + r0 + tx];   // t = r0+tx, constant per thread
#pragma unroll
    for (int j = 0; j < 4; j++)
        o[(long)(c0 + ty + 8 * j) * ostride + r0 + tx] =
            __float2half(__half2float(tile[tx][ty + 8 * j]) * rz);
}

// ------------------------- split-K reduce: out = p0 + p1 + bias -------------------------
__global__ void __launch_bounds__(256)
reduce_bias_kernel(const float4* __restrict__ p0, const float4* __restrict__ p1,
                   const float* __restrict__ bias, float4* __restrict__ out, int n4)
{
    const int i = blockIdx.x * 256 + threadIdx.x;
    if (i >= n4) return;
    const int col4 = i & (DMODEL / 4 - 1);
    const float4 b = ((const float4*)bias)[col4];
    float4 a = p0[i], c = p1[i];
    float4 r;
    r.x = a.x + c.x + b.x;
    r.y = a.y + c.y + b.y;
    r.z = a.z + c.z + b.z;
    r.w = a.w + c.w + b.w;
    out[i] = r;
}

// ------------------------- launch -------------------------
extern "C" void kernel_launch(void* const* d_in, const int* in_sizes, int n_in,
                              void* d_out, int out_size)
{
    const float* query = (const float*)d_in[0];
    const float* key_  = (const float*)d_in[1];
    const float* value = (const float*)d_in[2];
    const float* Wq    = (const float*)d_in[3];
    const float* bq    = (const float*)d_in[4];
    const float* Wk    = (const float*)d_in[5];
    const float* bk    = (const float*)d_in[6];
    const float* Wv    = (const float*)d_in[7];
    const float* bv    = (const float*)d_in[8];
    const float* Wo    = (const float*)d_in[9];
    const float* bo    = (const float*)d_in[10];
    float* out = (float*)d_out;

    fp16 *in16, *wT, *woT, *qkv, *vT, *E, *cc;
    float *bias, *Z, *part;
    cudaGetSymbolAddress((void**)&in16, g_in16);
    cudaGetSymbolAddress((void**)&wT,   g_wT);
    cudaGetSymbolAddress((void**)&woT,  g_woT);
    cudaGetSymbolAddress((void**)&bias, g_bias);
    cudaGetSymbolAddress((void**)&qkv,  g_qkv);
    cudaGetSymbolAddress((void**)&vT,   g_vT);
    cudaGetSymbolAddress((void**)&E,    g_E);
    cudaGetSymbolAddress((void**)&Z,    g_Z);
    cudaGetSymbolAddress((void**)&cc,   g_cc);
    cudaGetSymbolAddress((void**)&part, g_part);

    cudaFuncSetAttribute(mma_gemm<0>, cudaFuncAttributeMaxDynamicSharedMemorySize, GSMEM);
    cudaFuncSetAttribute(mma_gemm<1>, cudaFuncAttributeMaxDynamicSharedMemorySize, GSMEM);
    cudaFuncSetAttribute(mma_gemm<2>, cudaFuncAttributeMaxDynamicSharedMemorySize, GSMEM);
    cudaFuncSetAttribute(mma_gemm<3>, cudaFuncAttributeMaxDynamicSharedMemorySize, GSMEM);

    const float inv_sqrt_dk = 0.088388347648318447f;  // 1/sqrt(128)
    const long PLANE = (long)SEQ * DMODEL;

    // 0) inputs -> fp16 planes + bias pack + Z zero (one launch)
    {
        const int n8 = SEQ * DMODEL / 8;
        dim3 g(n8 / 256, 4);
        cvt3b_kernel<<<g, 256>>>((const float4*)query, (const float4*)key_,
                                 (const float4*)value, (uint4*)in16, n8,
                                 bq, bk, bv, bias, Z);
    }
    // 0b) all weight transposes (one launch)
    transpose_all_kernel<<<16384, 256>>>(Wq, Wk, Wv, Wo, wT, woT);

    // 1) merged projections: z = i*16 + h, grid (1, 32, 48)
    {
        dim3 g(1, SEQ / BM, 48);
        mma_gemm<2><<<g, 128, GSMEM>>>(in16, wT, bias, nullptr, qkv,
                                       DMODEL, DMODEL, PLANE, DMODEL, (long)DKH * DMODEL,
                                       DMODEL, PLANE, 0L, 1.0f, 1);
    }

    // 2) E[h][s][t] = exp(q_h[s,:].k_h[t,:] / sqrt(dk)) -> fp16; Z[h][t] += column sums
    {
        dim3 g(SEQ / BN, SEQ / BM, NHEADS);
        mma_gemm<3><<<g, 128, GSMEM>>>(qkv + 0 * PLANE, qkv + 1 * PLANE, bias /*unused*/, Z, E,
                                       DKH, DMODEL, 128L, DMODEL, 128L,
                                       SEQ, (long)SEQ * SEQ, 0L, inv_sqrt_dk, 0);
    }

    // 3) vT[h][n][t] = v[t][h*128+n] / Z[h][t]
    {
        dim3 g(DKH / 32, SEQ / 32, NHEADS);
        transpose_scale_kernel<<<g, 256>>>(qkv + 2 * PLANE, vT, Z,
                                           (long)DKH, DMODEL, (long)DKH * SEQ, SEQ);
    }

    // 4) concat[s][h*128+n] = sum_t E[h][s][t] * vT[h][n][t]  -> fp16
    {
        dim3 g(1, SEQ / BM, NHEADS);
        mma_gemm<1><<<g, 128, GSMEM>>>(E, vT, bias /*unused*/, nullptr, cc,
                                       SEQ, SEQ, (long)SEQ * SEQ, SEQ, (long)DKH * SEQ,
                                       DMODEL, 128L, 0L, 1.0f, 0);
    }

    // 5) out-proj split-K=2: part[z] = cc[:, z*1024:(z+1)*1024] @ woT[:, z*1024:(z+1)*1024]^T
    {
        dim3 g(DMODEL / BN, SEQ / BM, 2);
        mma_gemm<0><<<g, 128, GSMEM>>>(cc, woT, bias /*unused*/, part, nullptr,
                                       1024, DMODEL, 1024L, DMODEL, 1024L,
                                       DMODEL, PLANE, 0L, 1.0f, 0);
    }
    // 5b) out = part0 + part1 + bo
    {
        const int n4 = SEQ * DMODEL / 4;
        reduce_bias_kernel<<<n4 / 256, 256>>>((const float4*)part, (const float4*)(part + PLANE),
                                              bo, (float4*)out, n4);
    }
}